// round 14
// baseline (speedup 1.0000x reference)
#include <cuda_runtime.h>
#include <cuda_fp16.h>
#include <math.h>
#include <cstdint>

#define NTOK 8192      // B*N = 8*1024
#define DIMC 768
#define FC1OUT 5376
#define MLPH 3072
#define QKVD 2304
#define FC2IN 3840
#define FC2OUTF 768    // folded FC2 output (w2[c] + w2[c+768])

// ---------------- scratch (device globals; no allocation allowed) ----------------
__device__ float g_probsT[4 * NTOK];
__device__ float g_gate[4 * NTOK];
__device__ unsigned char g_sel[4 * NTOK];
__device__ float g_cS[NTOK * 8];                 // c0..c3, S0..S3 per token
__device__ __half g_yph[NTOK * DIMC];            // fp16(LN(x) * c_seg)  (fc1 A)
__device__ __half g_y2h[NTOK * FC2IN];           // fp16([gelu(mlp) | attn_out]) (fc2 A)
__device__ __half g_qkvh[NTOK * QKVD];           // fp16 qkv (q pre-scaled by 0.125)
__device__ __half g_w1h[FC1OUT * DIMC];          // fp16 weights
__device__ __half g_w2h[FC2OUTF * FC2IN];        // fp16 folded w2: w2[c]+w2[c+768]

// ================= PTX helpers =================
__device__ __forceinline__ void cp16(uint32_t dst, const void* src) {
    asm volatile("cp.async.cg.shared.global [%0], [%1], 16;" :: "r"(dst), "l"(src));
}
__device__ __forceinline__ void cp_commit() { asm volatile("cp.async.commit_group;"); }
template <int N>
__device__ __forceinline__ void cp_wait() { asm volatile("cp.async.wait_group %0;" :: "n"(N)); }

__device__ __forceinline__ void ldsm_x4(uint32_t& r0, uint32_t& r1, uint32_t& r2, uint32_t& r3, uint32_t addr) {
    asm volatile("ldmatrix.sync.aligned.m8n8.x4.shared.b16 {%0,%1,%2,%3}, [%4];"
                 : "=r"(r0), "=r"(r1), "=r"(r2), "=r"(r3) : "r"(addr));
}
__device__ __forceinline__ void ldsm_x2_trans(uint32_t& r0, uint32_t& r1, uint32_t addr) {
    asm volatile("ldmatrix.sync.aligned.m8n8.x2.trans.shared.b16 {%0,%1}, [%2];"
                 : "=r"(r0), "=r"(r1) : "r"(addr));
}
__device__ __forceinline__ void mma16816(float* c, const uint32_t* a, const uint32_t* b) {
    asm volatile("mma.sync.aligned.m16n8k16.row.col.f32.f16.f16.f32 "
                 "{%0,%1,%2,%3}, {%4,%5,%6,%7}, {%8,%9}, {%0,%1,%2,%3};"
                 : "+f"(c[0]), "+f"(c[1]), "+f"(c[2]), "+f"(c[3])
                 : "r"(a[0]), "r"(a[1]), "r"(a[2]), "r"(a[3]), "r"(b[0]), "r"(b[1]));
}
__device__ __forceinline__ uint32_t packh2(float a, float b) {
    __half2 h = __floats2half2_rn(a, b);
    return *(uint32_t*)&h;
}

// ---------------- K1: router logits + softmax (float4, warp/token) ----------------
__global__ __launch_bounds__(256) void router_kernel(const float* __restrict__ x,
                                                     const float* __restrict__ wr) {
    int warp = (blockIdx.x * blockDim.x + threadIdx.x) >> 5;
    int lane = threadIdx.x & 31;
    if (warp >= NTOK) return;
    const float4* xr = (const float4*)(x + (size_t)warp * DIMC);
    const float4* w0 = (const float4*)(wr);
    const float4* w1 = (const float4*)(wr + DIMC);
    const float4* w2 = (const float4*)(wr + 2 * DIMC);
    const float4* w3 = (const float4*)(wr + 3 * DIMC);
    float acc0 = 0.f, acc1 = 0.f, acc2 = 0.f, acc3 = 0.f;
    #pragma unroll
    for (int i = 0; i < 6; i++) {
        int idx = i * 32 + lane;
        float4 xv = xr[idx];
        float4 a = w0[idx], b = w1[idx], c = w2[idx], d = w3[idx];
        acc0 += xv.x * a.x + xv.y * a.y + xv.z * a.z + xv.w * a.w;
        acc1 += xv.x * b.x + xv.y * b.y + xv.z * b.z + xv.w * b.w;
        acc2 += xv.x * c.x + xv.y * c.y + xv.z * c.z + xv.w * c.w;
        acc3 += xv.x * d.x + xv.y * d.y + xv.z * d.z + xv.w * d.w;
    }
    #pragma unroll
    for (int o = 16; o; o >>= 1) {
        acc0 += __shfl_down_sync(0xffffffffu, acc0, o);
        acc1 += __shfl_down_sync(0xffffffffu, acc1, o);
        acc2 += __shfl_down_sync(0xffffffffu, acc2, o);
        acc3 += __shfl_down_sync(0xffffffffu, acc3, o);
    }
    if (lane == 0) {
        float mx = fmaxf(fmaxf(acc0, acc1), fmaxf(acc2, acc3));
        float p0 = expf(acc0 - mx), p1 = expf(acc1 - mx), p2 = expf(acc2 - mx), p3 = expf(acc3 - mx);
        float inv = 1.f / (p0 + p1 + p2 + p3);
        int b = warp >> 10, n = warp & 1023;
        g_probsT[(b * 4 + 0) * 1024 + n] = p0 * inv;
        g_probsT[(b * 4 + 1) * 1024 + n] = p1 * inv;
        g_probsT[(b * 4 + 2) * 1024 + n] = p2 * inv;
        g_probsT[(b * 4 + 3) * 1024 + n] = p3 * inv;
    }
}

// ---------------- K2: top-512 per (b,e) by rank counting (float4 inner loop) ----------------
__global__ __launch_bounds__(1024) void topk_kernel() {
    __shared__ float sp[1024];
    int be = blockIdx.x;
    int i = threadIdx.x;
    float p = g_probsT[be * 1024 + i];
    sp[i] = p;
    __syncthreads();
    const float4* sp4 = (const float4*)sp;
    int cnt = 0;
    #pragma unroll 4
    for (int j4 = 0; j4 < 256; j4++) {
        float4 q = sp4[j4];
        int j = j4 * 4;
        cnt += (q.x > p) || (q.x == p && (j + 0) < i);
        cnt += (q.y > p) || (q.y == p && (j + 1) < i);
        cnt += (q.z > p) || (q.z == p && (j + 2) < i);
        cnt += (q.w > p) || (q.w == p && (j + 3) < i);
    }
    bool sel = cnt < 512;
    g_gate[be * 1024 + i] = sel ? p : 0.f;
    g_sel[be * 1024 + i] = sel ? 1 : 0;
}

// ---------------- K3+K4 fused: per-token stats + LayerNorm * c_seg -> fp16 ----------------
__global__ __launch_bounds__(256) void ln_kernel(const float* __restrict__ x,
                                                 const float* __restrict__ gamma,
                                                 const float* __restrict__ beta) {
    int warp = (blockIdx.x * blockDim.x + threadIdx.x) >> 5;
    int lane = threadIdx.x & 31;
    if (warp >= NTOK) return;

    float c0, c1, c2, c3;
    if (lane == 0) {
        int b = warp >> 10, n = warp & 1023;
        float cs = 0.f, ss = 0.f;
        float cArr[4], SArr[4];
        #pragma unroll
        for (int e = 3; e >= 0; e--) {
            cs += (float)g_sel[(b * 4 + e) * 1024 + n];
            ss += g_gate[(b * 4 + e) * 1024 + n];
            cArr[e] = cs;
            SArr[e] = ss;
        }
        #pragma unroll
        for (int k = 0; k < 4; k++) {
            g_cS[warp * 8 + k] = cArr[k];
            g_cS[warp * 8 + 4 + k] = SArr[k];
        }
        c0 = cArr[0]; c1 = cArr[1]; c2 = cArr[2]; c3 = cArr[3];
    }
    c0 = __shfl_sync(0xffffffffu, c0, 0);
    c1 = __shfl_sync(0xffffffffu, c1, 0);
    c2 = __shfl_sync(0xffffffffu, c2, 0);
    c3 = __shfl_sync(0xffffffffu, c3, 0);

    const float4* xr = (const float4*)(x + (size_t)warp * DIMC);
    float4 v[6];
    float s = 0.f, s2 = 0.f;
    #pragma unroll
    for (int i = 0; i < 6; i++) {
        v[i] = xr[i * 32 + lane];
        s += v[i].x + v[i].y + v[i].z + v[i].w;
        s2 += v[i].x * v[i].x + v[i].y * v[i].y + v[i].z * v[i].z + v[i].w * v[i].w;
    }
    #pragma unroll
    for (int o = 16; o; o >>= 1) {
        s += __shfl_xor_sync(0xffffffffu, s, o);
        s2 += __shfl_xor_sync(0xffffffffu, s2, o);
    }
    float mu = s * (1.f / 768.f);
    float var = s2 * (1.f / 768.f) - mu * mu;
    float rstd = rsqrtf(var + 1e-6f);
    const float4* gm = (const float4*)gamma;
    const float4* bt = (const float4*)beta;
    #pragma unroll
    for (int i = 0; i < 6; i++) {
        int idx = i * 32 + lane;
        int d = idx * 4;
        float c = (d < 96) ? c0 : (d < 192) ? c1 : (d < 384) ? c2 : c3;
        float4 g = gm[idx], b = bt[idx];
        float r0 = ((v[i].x - mu) * rstd * g.x + b.x) * c;
        float r1 = ((v[i].y - mu) * rstd * g.y + b.y) * c;
        float r2 = ((v[i].z - mu) * rstd * g.z + b.z) * c;
        float r3 = ((v[i].w - mu) * rstd * g.w + b.w) * c;
        __half2 h0 = __floats2half2_rn(r0, r1);
        __half2 h1 = __floats2half2_rn(r2, r3);
        uint2 pk = make_uint2(*(uint32_t*)&h0, *(uint32_t*)&h1);
        *(uint2*)&g_yph[(size_t)warp * DIMC + d] = pk;
    }
}

// ---------------- weight conversion: w1 -> fp16, w2 folded (c + c+768) -> fp16 ----------------
__global__ void h_cvt_kernel(const float* __restrict__ w1, const float* __restrict__ w2) {
    constexpr int N1 = FC1OUT * DIMC / 4;
    constexpr int N2 = FC2OUTF * FC2IN / 4;
    int i = blockIdx.x * blockDim.x + threadIdx.x;
    if (i < N1) {
        float4 v = ((const float4*)w1)[i];
        __half2 h01 = __floats2half2_rn(v.x, v.y);
        __half2 h23 = __floats2half2_rn(v.z, v.w);
        ((__half2*)g_w1h)[i * 2] = h01;
        ((__half2*)g_w1h)[i * 2 + 1] = h23;
    } else if (i < N1 + N2) {
        int idx = i - N1;
        float4 a = ((const float4*)w2)[idx];
        float4 b = ((const float4*)w2)[idx + N2];
        a.x += b.x; a.y += b.y; a.z += b.z; a.w += b.w;
        __half2 h01 = __floats2half2_rn(a.x, a.y);
        __half2 h23 = __floats2half2_rn(a.z, a.w);
        ((__half2*)g_w2h)[idx * 2] = h01;
        ((__half2*)g_w2h)[idx * 2 + 1] = h23;
    }
}

// ================ HMMA GEMM 128x128, BK=32, cp.async 3-stage (proven schedule) ================
// MODE 1: A=g_yph K=768,  W=g_w1h (N=5376): gelu->g_y2h / ->g_qkvh; bias c0*b1
// MODE 2: A=g_y2h K=3840, W=g_w2h (N=768 folded): out = x + (acc + b2[o]+b2[o+768]) * S_seg(o)
template <int MODE>
__global__ __launch_bounds__(256) void gemm_mma(const float* __restrict__ bias,
                                                const float* __restrict__ xres,
                                                float* __restrict__ outp) {
    constexpr int KDIM = (MODE == 1) ? DIMC : FC2IN;
    constexpr int NT = KDIM / 32;
    constexpr int STAGES = 3;
    constexpr uint32_t STAGE_B = 20480;
    const __half* __restrict__ A = (MODE == 1) ? (const __half*)g_yph : (const __half*)g_y2h;
    const __half* __restrict__ Wh = (MODE == 1) ? (const __half*)g_w1h : (const __half*)g_w2h;

    extern __shared__ char smem[];
    uint32_t sb = (uint32_t)__cvta_generic_to_shared(smem);

    int tid = threadIdx.x, wid = tid >> 5, lane = tid & 31;
    int m0 = blockIdx.y * 128, n0 = blockIdx.x * 128;
    int wm = wid & 1, wn = wid >> 1;

    int cr = tid >> 2, cc = (tid & 3) * 8;
    const __half* Ag0 = A + (size_t)(m0 + cr) * KDIM + cc;
    const __half* Ag1 = A + (size_t)(m0 + cr + 64) * KDIM + cc;
    const __half* Bg0 = Wh + (size_t)(n0 + cr) * KDIM + cc;
    const __half* Bg1 = Wh + (size_t)(n0 + cr + 64) * KDIM + cc;
    uint32_t sA0 = sb + cr * 80 + cc * 2;
    uint32_t sA1 = sA0 + 64 * 80;
    uint32_t sB0 = sb + 10240 + cr * 80 + cc * 2;
    uint32_t sB1 = sB0 + 64 * 80;

    float acc[4][4][4];
    #pragma unroll
    for (int i = 0; i < 4; i++)
        #pragma unroll
        for (int j = 0; j < 4; j++)
            #pragma unroll
            for (int t = 0; t < 4; t++) acc[i][j][t] = 0.f;

    #pragma unroll
    for (int s = 0; s < STAGES - 1; s++) {
        uint32_t off = s * STAGE_B;
        cp16(sA0 + off, Ag0 + s * 32);
        cp16(sA1 + off, Ag1 + s * 32);
        cp16(sB0 + off, Bg0 + s * 32);
        cp16(sB1 + off, Bg1 + s * 32);
        cp_commit();
    }

    for (int kt = 0; kt < NT; kt++) {
        cp_wait<STAGES - 2>();
        __syncthreads();

        uint32_t abase = sb + (uint32_t)(kt % STAGES) * STAGE_B;
        uint32_t bbase = abase + 10240;
        #pragma unroll
        for (int ks = 0; ks < 2; ks++) {
            uint32_t af[4][4];
            #pragma unroll
            for (int i = 0; i < 4; i++) {
                uint32_t r = wm * 64 + i * 16 + (lane & 15);
                uint32_t c = ks * 16 + (lane >> 4) * 8;
                ldsm_x4(af[i][0], af[i][1], af[i][2], af[i][3], abase + (r * 40 + c) * 2);
            }
            uint32_t bf[4][2];
            #pragma unroll
            for (int jp = 0; jp < 2; jp++) {
                uint32_t r = wn * 32 + jp * 16 + ((lane >> 4) & 1) * 8 + (lane & 7);
                uint32_t c = ks * 16 + ((lane >> 3) & 1) * 8;
                ldsm_x4(bf[2 * jp][0], bf[2 * jp][1], bf[2 * jp + 1][0], bf[2 * jp + 1][1],
                        bbase + (r * 40 + c) * 2);
            }
            #pragma unroll
            for (int i = 0; i < 4; i++)
                #pragma unroll
                for (int j = 0; j < 4; j++) mma16816(acc[i][j], af[i], bf[j]);
        }

        int nk = kt + STAGES - 1;
        if (nk < NT) {
            uint32_t off = (uint32_t)(nk % STAGES) * STAGE_B;
            cp16(sA0 + off, Ag0 + nk * 32);
            cp16(sA1 + off, Ag1 + nk * 32);
            cp16(sB0 + off, Bg0 + nk * 32);
            cp16(sB1 + off, Bg1 + nk * 32);
        }
        cp_commit();
    }

    #pragma unroll
    for (int i = 0; i < 4; i++) {
        int m_a = m0 + wm * 64 + i * 16 + (lane >> 2);
        int m_b = m_a + 8;
        if (MODE == 1) {
            float c0a = g_cS[m_a * 8], c0b = g_cS[m_b * 8];
            #pragma unroll
            for (int j = 0; j < 4; j++) {
                int f = n0 + wn * 32 + j * 8 + (lane & 3) * 2;
                float b0v = bias[f], b1v = bias[f + 1];
                float v0 = acc[i][j][0] + c0a * b0v;
                float v1 = acc[i][j][1] + c0a * b1v;
                float v2 = acc[i][j][2] + c0b * b0v;
                float v3 = acc[i][j][3] + c0b * b1v;
                if (f < MLPH) {
                    const float is2 = 0.70710678118654752f;
                    v0 = 0.5f * v0 * (1.f + erff(v0 * is2));
                    v1 = 0.5f * v1 * (1.f + erff(v1 * is2));
                    v2 = 0.5f * v2 * (1.f + erff(v2 * is2));
                    v3 = 0.5f * v3 * (1.f + erff(v3 * is2));
                    *(__half2*)&g_y2h[(size_t)m_a * FC2IN + f] = __floats2half2_rn(v0, v1);
                    *(__half2*)&g_y2h[(size_t)m_b * FC2IN + f] = __floats2half2_rn(v2, v3);
                } else {
                    int fq = f - MLPH;
                    float sc = (fq < 768) ? 0.125f : 1.f;   // pre-scale q by 1/sqrt(64)
                    *(__half2*)&g_qkvh[(size_t)m_a * QKVD + fq] = __floats2half2_rn(v0 * sc, v1 * sc);
                    *(__half2*)&g_qkvh[(size_t)m_b * QKVD + fq] = __floats2half2_rn(v2 * sc, v3 * sc);
                }
            }
        } else {
            #pragma unroll
            for (int j = 0; j < 4; j++) {
                int o = n0 + wn * 32 + j * 8 + (lane & 3) * 2;   // 0..767
                int seg = (o >= 384) ? 3 : (o >= 192) ? 2 : (o >= 96) ? 1 : 0;
                float Sa = g_cS[m_a * 8 + 4 + seg], Sb = g_cS[m_b * 8 + 4 + seg];
                float b0v = bias[o] + bias[o + 768];
                float b1v = bias[o + 1] + bias[o + 769];
                float2 xa = *(const float2*)&xres[(size_t)m_a * DIMC + o];
                float2 xb = *(const float2*)&xres[(size_t)m_b * DIMC + o];
                *(float2*)&outp[(size_t)m_a * DIMC + o] =
                    make_float2(xa.x + (acc[i][j][0] + b0v) * Sa, xa.y + (acc[i][j][1] + b1v) * Sa);
                *(float2*)&outp[(size_t)m_b * DIMC + o] =
                    make_float2(xb.x + (acc[i][j][2] + b0v) * Sb, xb.y + (acc[i][j][3] + b1v) * Sb);
            }
        }
    }
}

// ---------------- K6: flash attention on HMMA (proven static version) ----------------
__global__ __launch_bounds__(256) void fattn_kernel() {
    __shared__ __half Qs[128][72];
    __shared__ __half Ks[64][72];
    __shared__ __half Vs[64][72];
    int bh = blockIdx.x;
    int b = bh / 12, h = bh % 12;
    int q0 = blockIdx.y * 128;
    int tid = threadIdx.x, wid = tid >> 5, lane = tid & 31;
    const __half* base = g_qkvh + (size_t)b * 1024 * QKVD + h * 64;

    #pragma unroll
    for (int i = 0; i < 4; i++) {
        int chunk = i * 256 + tid;
        int r = chunk >> 3, c8 = (chunk & 7) * 8;
        *(uint4*)&Qs[r][c8] = *(const uint4*)(base + (size_t)(q0 + r) * QKVD + c8);
    }
    __syncthreads();

    uint32_t qbase = (uint32_t)__cvta_generic_to_shared(&Qs[0][0]);
    uint32_t kbase = (uint32_t)__cvta_generic_to_shared(&Ks[0][0]);
    uint32_t vbase = (uint32_t)__cvta_generic_to_shared(&Vs[0][0]);

    uint32_t qf[4][4];
    #pragma unroll
    for (int kk = 0; kk < 4; kk++) {
        uint32_t addr = qbase + (((uint32_t)(wid * 16 + (lane & 15))) * 72 + kk * 16 + (lane >> 4) * 8) * 2;
        ldsm_x4(qf[kk][0], qf[kk][1], qf[kk][2], qf[kk][3], addr);
    }

    float m0 = -1e30f, m1 = -1e30f, l0 = 0.f, l1 = 0.f;
    float o[8][4];
    #pragma unroll
    for (int dj = 0; dj < 8; dj++)
        #pragma unroll
        for (int t = 0; t < 4; t++) o[dj][t] = 0.f;

    for (int kt = 0; kt < 16; kt++) {
        __syncthreads();
        #pragma unroll
        for (int i = 0; i < 2; i++) {
            int chunk = i * 256 + tid;
            int r = chunk >> 3, c8 = (chunk & 7) * 8;
            const __half* rowp = base + (size_t)(kt * 64 + r) * QKVD + c8;
            *(uint4*)&Ks[r][c8] = *(const uint4*)(rowp + 768);
            *(uint4*)&Vs[r][c8] = *(const uint4*)(rowp + 1536);
        }
        __syncthreads();

        float s[8][4];
        #pragma unroll
        for (int j = 0; j < 8; j++)
            #pragma unroll
            for (int t = 0; t < 4; t++) s[j][t] = 0.f;
        #pragma unroll
        for (int kk = 0; kk < 4; kk++) {
            #pragma unroll
            for (int jp = 0; jp < 4; jp++) {
                uint32_t bf2[4];
                uint32_t r = (uint32_t)(jp * 16 + ((lane >> 4) & 1) * 8 + (lane & 7));
                uint32_t c = kk * 16 + ((lane >> 3) & 1) * 8;
                ldsm_x4(bf2[0], bf2[1], bf2[2], bf2[3], kbase + (r * 72 + c) * 2);
                mma16816(s[2 * jp], qf[kk], bf2);
                mma16816(s[2 * jp + 1], qf[kk], bf2 + 2);
            }
        }

        float tm0 = -1e30f, tm1 = -1e30f;
        #pragma unroll
        for (int j = 0; j < 8; j++) {
            tm0 = fmaxf(tm0, fmaxf(s[j][0], s[j][1]));
            tm1 = fmaxf(tm1, fmaxf(s[j][2], s[j][3]));
        }
        tm0 = fmaxf(tm0, __shfl_xor_sync(0xffffffffu, tm0, 1));
        tm0 = fmaxf(tm0, __shfl_xor_sync(0xffffffffu, tm0, 2));
        tm1 = fmaxf(tm1, __shfl_xor_sync(0xffffffffu, tm1, 1));
        tm1 = fmaxf(tm1, __shfl_xor_sync(0xffffffffu, tm1, 2));
        float nm0 = fmaxf(m0, tm0), nm1 = fmaxf(m1, tm1);
        float corr0 = __expf(m0 - nm0), corr1 = __expf(m1 - nm1);
        m0 = nm0; m1 = nm1;

        uint32_t plo[8], phi[8];
        float ps0 = 0.f, ps1 = 0.f;
        #pragma unroll
        for (int j = 0; j < 8; j++) {
            float p0 = __expf(s[j][0] - m0), p1 = __expf(s[j][1] - m0);
            float p2 = __expf(s[j][2] - m1), p3 = __expf(s[j][3] - m1);
            ps0 += p0 + p1; ps1 += p2 + p3;
            plo[j] = packh2(p0, p1);
            phi[j] = packh2(p2, p3);
        }
        l0 = l0 * corr0 + ps0;
        l1 = l1 * corr1 + ps1;
        #pragma unroll
        for (int dj = 0; dj < 8; dj++) {
            o[dj][0] *= corr0; o[dj][1] *= corr0;
            o[dj][2] *= corr1; o[dj][3] *= corr1;
        }

        #pragma unroll
        for (int jj = 0; jj < 4; jj++) {
            uint32_t a[4] = {plo[2 * jj], phi[2 * jj], plo[2 * jj + 1], phi[2 * jj + 1]};
            #pragma unroll
            for (int dj = 0; dj < 8; dj++) {
                uint32_t bfv[2];
                uint32_t addr = vbase + (((uint32_t)(jj * 16 + (lane & 15))) * 72 + dj * 8) * 2;
                ldsm_x2_trans(bfv[0], bfv[1], addr);
                mma16816(o[dj], a, bfv);
            }
        }
    }

    l0 += __shfl_xor_sync(0xffffffffu, l0, 1);
    l0 += __shfl_xor_sync(0xffffffffu, l0, 2);
    l1 += __shfl_xor_sync(0xffffffffu, l1, 1);
    l1 += __shfl_xor_sync(0xffffffffu, l1, 2);
    float inv0 = 1.f / l0, inv1 = 1.f / l1;
    int r0 = q0 + wid * 16 + (lane >> 2);
    size_t m_a = (size_t)(b * 1024 + r0) * FC2IN + MLPH + h * 64;
    size_t m_b = m_a + (size_t)8 * FC2IN;
    #pragma unroll
    for (int dj = 0; dj < 8; dj++) {
        int d = dj * 8 + (lane & 3) * 2;
        *(__half2*)&g_y2h[m_a + d] = __floats2half2_rn(o[dj][0] * inv0, o[dj][1] * inv0);
        *(__half2*)&g_y2h[m_b + d] = __floats2half2_rn(o[dj][2] * inv1, o[dj][3] * inv1);
    }
}

// ---------------- launch ----------------
extern "C" void kernel_launch(void* const* d_in, const int* in_sizes, int n_in,
                              void* d_out, int out_size) {
    const float* x = (const float*)d_in[0];
    const float* wr = (const float*)d_in[1];
    const float* gamma = (const float*)d_in[2];
    const float* beta = (const float*)d_in[3];
    const float* w1 = (const float*)d_in[4];
    const float* b1 = (const float*)d_in[5];
    const float* w2 = (const float*)d_in[6];
    const float* b2 = (const float*)d_in[7];
    float* out = (float*)d_out;

    // one-time side stream + events (created outside any capture; fork-join is capturable)
    static cudaStream_t s2 = nullptr;
    static cudaEvent_t evFork = nullptr, evJoin = nullptr;
    if (!s2) {
        cudaStreamCreateWithFlags(&s2, cudaStreamNonBlocking);
        cudaEventCreateWithFlags(&evFork, cudaEventDisableTiming);
        cudaEventCreateWithFlags(&evJoin, cudaEventDisableTiming);
        cudaFuncSetAttribute(gemm_mma<1>, cudaFuncAttributeMaxDynamicSharedMemorySize, 61440);
        cudaFuncSetAttribute(gemm_mma<2>, cudaFuncAttributeMaxDynamicSharedMemorySize, 61440);
    }

    constexpr int NCVT = FC1OUT * DIMC / 4 + FC2OUTF * FC2IN / 4;

    // fork: weight conversion runs concurrently with router->topk->ln chain
    cudaEventRecord(evFork, 0);
    cudaStreamWaitEvent(s2, evFork, 0);
    h_cvt_kernel<<<(NCVT + 255) / 256, 256, 0, s2>>>(w1, w2);
    cudaEventRecord(evJoin, s2);

    router_kernel<<<NTOK / 8, 256>>>(x, wr);
    topk_kernel<<<32, 1024>>>();
    ln_kernel<<<NTOK / 8, 256>>>(x, gamma, beta);

    // join before gemm1 (needs both g_yph and g_w1h)
    cudaStreamWaitEvent(0, evJoin, 0);

    gemm_mma<1><<<dim3(FC1OUT / 128, NTOK / 128), 256, 61440>>>(b1, nullptr, nullptr);
    fattn_kernel<<<dim3(96, 8), 256>>>();
    gemm_mma<2><<<dim3(FC2OUTF / 128, NTOK / 128), 256, 61440>>>(b2, x, out);
}

// round 15
// speedup vs baseline: 1.0143x; 1.0143x over previous
#include <cuda_runtime.h>
#include <cuda_fp16.h>
#include <math.h>
#include <cstdint>

#define NTOK 8192      // B*N = 8*1024
#define DIMC 768
#define FC1OUT 5376
#define MLPH 3072
#define QKVD 2304
#define FC2IN 3840
#define FC2OUTF 768    // folded FC2 output (w2[c] + w2[c+768])

// ---------------- scratch (device globals; no allocation allowed) ----------------
__device__ float g_probsT[4 * NTOK];
__device__ float g_gate[4 * NTOK];
__device__ unsigned char g_sel[4 * NTOK];
__device__ float g_cS[NTOK * 8];                 // c0..c3, S0..S3 per token
__device__ __half g_yph[NTOK * DIMC];            // fp16(LN(x) * c_seg)  (fc1 A)
__device__ __half g_y2h[NTOK * FC2IN];           // fp16([gelu(mlp) | attn_out]) (fc2 A)
__device__ __half g_qkvh[NTOK * QKVD];           // fp16 qkv (q pre-scaled by 0.125)
__device__ __half g_w1h[FC1OUT * DIMC];          // fp16 weights
__device__ __half g_w2h[FC2OUTF * FC2IN];        // fp16 folded w2: w2[c]+w2[c+768]
__device__ float g_part[NTOK * FC2OUTF];         // fc2 partial over K=0..3071

// ================= PTX helpers =================
__device__ __forceinline__ void cp16(uint32_t dst, const void* src) {
    asm volatile("cp.async.cg.shared.global [%0], [%1], 16;" :: "r"(dst), "l"(src));
}
__device__ __forceinline__ void cp_commit() { asm volatile("cp.async.commit_group;"); }
template <int N>
__device__ __forceinline__ void cp_wait() { asm volatile("cp.async.wait_group %0;" :: "n"(N)); }

__device__ __forceinline__ void ldsm_x4(uint32_t& r0, uint32_t& r1, uint32_t& r2, uint32_t& r3, uint32_t addr) {
    asm volatile("ldmatrix.sync.aligned.m8n8.x4.shared.b16 {%0,%1,%2,%3}, [%4];"
                 : "=r"(r0), "=r"(r1), "=r"(r2), "=r"(r3) : "r"(addr));
}
__device__ __forceinline__ void ldsm_x2_trans(uint32_t& r0, uint32_t& r1, uint32_t addr) {
    asm volatile("ldmatrix.sync.aligned.m8n8.x2.trans.shared.b16 {%0,%1}, [%2];"
                 : "=r"(r0), "=r"(r1) : "r"(addr));
}
__device__ __forceinline__ void mma16816(float* c, const uint32_t* a, const uint32_t* b) {
    asm volatile("mma.sync.aligned.m16n8k16.row.col.f32.f16.f16.f32 "
                 "{%0,%1,%2,%3}, {%4,%5,%6,%7}, {%8,%9}, {%0,%1,%2,%3};"
                 : "+f"(c[0]), "+f"(c[1]), "+f"(c[2]), "+f"(c[3])
                 : "r"(a[0]), "r"(a[1]), "r"(a[2]), "r"(a[3]), "r"(b[0]), "r"(b[1]));
}
__device__ __forceinline__ uint32_t packh2(float a, float b) {
    __half2 h = __floats2half2_rn(a, b);
    return *(uint32_t*)&h;
}

// ---------------- K1: router logits + softmax (float4, warp/token) ----------------
__global__ __launch_bounds__(256) void router_kernel(const float* __restrict__ x,
                                                     const float* __restrict__ wr) {
    int warp = (blockIdx.x * blockDim.x + threadIdx.x) >> 5;
    int lane = threadIdx.x & 31;
    if (warp >= NTOK) return;
    const float4* xr = (const float4*)(x + (size_t)warp * DIMC);
    const float4* w0 = (const float4*)(wr);
    const float4* w1 = (const float4*)(wr + DIMC);
    const float4* w2 = (const float4*)(wr + 2 * DIMC);
    const float4* w3 = (const float4*)(wr + 3 * DIMC);
    float acc0 = 0.f, acc1 = 0.f, acc2 = 0.f, acc3 = 0.f;
    #pragma unroll
    for (int i = 0; i < 6; i++) {
        int idx = i * 32 + lane;
        float4 xv = xr[idx];
        float4 a = w0[idx], b = w1[idx], c = w2[idx], d = w3[idx];
        acc0 += xv.x * a.x + xv.y * a.y + xv.z * a.z + xv.w * a.w;
        acc1 += xv.x * b.x + xv.y * b.y + xv.z * b.z + xv.w * b.w;
        acc2 += xv.x * c.x + xv.y * c.y + xv.z * c.z + xv.w * c.w;
        acc3 += xv.x * d.x + xv.y * d.y + xv.z * d.z + xv.w * d.w;
    }
    #pragma unroll
    for (int o = 16; o; o >>= 1) {
        acc0 += __shfl_down_sync(0xffffffffu, acc0, o);
        acc1 += __shfl_down_sync(0xffffffffu, acc1, o);
        acc2 += __shfl_down_sync(0xffffffffu, acc2, o);
        acc3 += __shfl_down_sync(0xffffffffu, acc3, o);
    }
    if (lane == 0) {
        float mx = fmaxf(fmaxf(acc0, acc1), fmaxf(acc2, acc3));
        float p0 = expf(acc0 - mx), p1 = expf(acc1 - mx), p2 = expf(acc2 - mx), p3 = expf(acc3 - mx);
        float inv = 1.f / (p0 + p1 + p2 + p3);
        int b = warp >> 10, n = warp & 1023;
        g_probsT[(b * 4 + 0) * 1024 + n] = p0 * inv;
        g_probsT[(b * 4 + 1) * 1024 + n] = p1 * inv;
        g_probsT[(b * 4 + 2) * 1024 + n] = p2 * inv;
        g_probsT[(b * 4 + 3) * 1024 + n] = p3 * inv;
    }
}

// ---------------- K2: top-512 per (b,e) by rank counting (float4 inner loop) ----------------
__global__ __launch_bounds__(1024) void topk_kernel() {
    __shared__ float sp[1024];
    int be = blockIdx.x;
    int i = threadIdx.x;
    float p = g_probsT[be * 1024 + i];
    sp[i] = p;
    __syncthreads();
    const float4* sp4 = (const float4*)sp;
    int cnt = 0;
    #pragma unroll 4
    for (int j4 = 0; j4 < 256; j4++) {
        float4 q = sp4[j4];
        int j = j4 * 4;
        cnt += (q.x > p) || (q.x == p && (j + 0) < i);
        cnt += (q.y > p) || (q.y == p && (j + 1) < i);
        cnt += (q.z > p) || (q.z == p && (j + 2) < i);
        cnt += (q.w > p) || (q.w == p && (j + 3) < i);
    }
    bool sel = cnt < 512;
    g_gate[be * 1024 + i] = sel ? p : 0.f;
    g_sel[be * 1024 + i] = sel ? 1 : 0;
}

// ---------------- K3+K4 fused: per-token stats + LayerNorm * c_seg -> fp16 ----------------
__global__ __launch_bounds__(256) void ln_kernel(const float* __restrict__ x,
                                                 const float* __restrict__ gamma,
                                                 const float* __restrict__ beta) {
    int warp = (blockIdx.x * blockDim.x + threadIdx.x) >> 5;
    int lane = threadIdx.x & 31;
    if (warp >= NTOK) return;

    float c0, c1, c2, c3;
    if (lane == 0) {
        int b = warp >> 10, n = warp & 1023;
        float cs = 0.f, ss = 0.f;
        float cArr[4], SArr[4];
        #pragma unroll
        for (int e = 3; e >= 0; e--) {
            cs += (float)g_sel[(b * 4 + e) * 1024 + n];
            ss += g_gate[(b * 4 + e) * 1024 + n];
            cArr[e] = cs;
            SArr[e] = ss;
        }
        #pragma unroll
        for (int k = 0; k < 4; k++) {
            g_cS[warp * 8 + k] = cArr[k];
            g_cS[warp * 8 + 4 + k] = SArr[k];
        }
        c0 = cArr[0]; c1 = cArr[1]; c2 = cArr[2]; c3 = cArr[3];
    }
    c0 = __shfl_sync(0xffffffffu, c0, 0);
    c1 = __shfl_sync(0xffffffffu, c1, 0);
    c2 = __shfl_sync(0xffffffffu, c2, 0);
    c3 = __shfl_sync(0xffffffffu, c3, 0);

    const float4* xr = (const float4*)(x + (size_t)warp * DIMC);
    float4 v[6];
    float s = 0.f, s2 = 0.f;
    #pragma unroll
    for (int i = 0; i < 6; i++) {
        v[i] = xr[i * 32 + lane];
        s += v[i].x + v[i].y + v[i].z + v[i].w;
        s2 += v[i].x * v[i].x + v[i].y * v[i].y + v[i].z * v[i].z + v[i].w * v[i].w;
    }
    #pragma unroll
    for (int o = 16; o; o >>= 1) {
        s += __shfl_xor_sync(0xffffffffu, s, o);
        s2 += __shfl_xor_sync(0xffffffffu, s2, o);
    }
    float mu = s * (1.f / 768.f);
    float var = s2 * (1.f / 768.f) - mu * mu;
    float rstd = rsqrtf(var + 1e-6f);
    const float4* gm = (const float4*)gamma;
    const float4* bt = (const float4*)beta;
    #pragma unroll
    for (int i = 0; i < 6; i++) {
        int idx = i * 32 + lane;
        int d = idx * 4;
        float c = (d < 96) ? c0 : (d < 192) ? c1 : (d < 384) ? c2 : c3;
        float4 g = gm[idx], b = bt[idx];
        float r0 = ((v[i].x - mu) * rstd * g.x + b.x) * c;
        float r1 = ((v[i].y - mu) * rstd * g.y + b.y) * c;
        float r2 = ((v[i].z - mu) * rstd * g.z + b.z) * c;
        float r3 = ((v[i].w - mu) * rstd * g.w + b.w) * c;
        __half2 h0 = __floats2half2_rn(r0, r1);
        __half2 h1 = __floats2half2_rn(r2, r3);
        uint2 pk = make_uint2(*(uint32_t*)&h0, *(uint32_t*)&h1);
        *(uint2*)&g_yph[(size_t)warp * DIMC + d] = pk;
    }
}

// ---------------- weight conversion: w1 -> fp16, w2 folded (c + c+768) -> fp16 ----------------
__global__ void h_cvt_kernel(const float* __restrict__ w1, const float* __restrict__ w2) {
    constexpr int N1 = FC1OUT * DIMC / 4;
    constexpr int N2 = FC2OUTF * FC2IN / 4;
    int i = blockIdx.x * blockDim.x + threadIdx.x;
    if (i < N1) {
        float4 v = ((const float4*)w1)[i];
        __half2 h01 = __floats2half2_rn(v.x, v.y);
        __half2 h23 = __floats2half2_rn(v.z, v.w);
        ((__half2*)g_w1h)[i * 2] = h01;
        ((__half2*)g_w1h)[i * 2 + 1] = h23;
    } else if (i < N1 + N2) {
        int idx = i - N1;
        float4 a = ((const float4*)w2)[idx];
        float4 b = ((const float4*)w2)[idx + N2];
        a.x += b.x; a.y += b.y; a.z += b.z; a.w += b.w;
        __half2 h01 = __floats2half2_rn(a.x, a.y);
        __half2 h23 = __floats2half2_rn(a.z, a.w);
        ((__half2*)g_w2h)[idx * 2] = h01;
        ((__half2*)g_w2h)[idx * 2 + 1] = h23;
    }
}

// ================ HMMA GEMM 128x128, BK=32, cp.async 3-stage (proven schedule) ================
// MODE 1: A=g_yph K=768, W=g_w1h: gelu->g_y2h / ->g_qkvh; bias c0*b1
// MODE 2: fc2 partial over K=0..3071 (MLP range, ready after gemm1): raw acc -> g_part
// MODE 3: fc2 tail K=3072..3839 (attn range): out = x + (acc + part + b2fold) * S_seg
template <int MODE>
__global__ __launch_bounds__(256) void gemm_mma(const float* __restrict__ bias,
                                                const float* __restrict__ xres,
                                                float* __restrict__ outp) {
    constexpr int KDIM = (MODE == 1) ? DIMC : FC2IN;
    constexpr int KOFF = (MODE == 3) ? MLPH : 0;
    constexpr int NT = (MODE == 1) ? (DIMC / 32) : (MODE == 2) ? (MLPH / 32) : ((FC2IN - MLPH) / 32);
    constexpr int STAGES = 3;
    constexpr uint32_t STAGE_B = 20480;
    const __half* __restrict__ A = (MODE == 1) ? (const __half*)g_yph : (const __half*)g_y2h + KOFF;
    const __half* __restrict__ Wh = (MODE == 1) ? (const __half*)g_w1h : (const __half*)g_w2h + KOFF;

    extern __shared__ char smem[];
    uint32_t sb = (uint32_t)__cvta_generic_to_shared(smem);

    int tid = threadIdx.x, wid = tid >> 5, lane = tid & 31;
    int m0 = blockIdx.y * 128, n0 = blockIdx.x * 128;
    int wm = wid & 1, wn = wid >> 1;

    int cr = tid >> 2, cc = (tid & 3) * 8;
    const __half* Ag0 = A + (size_t)(m0 + cr) * KDIM + cc;
    const __half* Ag1 = A + (size_t)(m0 + cr + 64) * KDIM + cc;
    const __half* Bg0 = Wh + (size_t)(n0 + cr) * KDIM + cc;
    const __half* Bg1 = Wh + (size_t)(n0 + cr + 64) * KDIM + cc;
    uint32_t sA0 = sb + cr * 80 + cc * 2;
    uint32_t sA1 = sA0 + 64 * 80;
    uint32_t sB0 = sb + 10240 + cr * 80 + cc * 2;
    uint32_t sB1 = sB0 + 64 * 80;

    float acc[4][4][4];
    #pragma unroll
    for (int i = 0; i < 4; i++)
        #pragma unroll
        for (int j = 0; j < 4; j++)
            #pragma unroll
            for (int t = 0; t < 4; t++) acc[i][j][t] = 0.f;

    #pragma unroll
    for (int s = 0; s < STAGES - 1; s++) {
        uint32_t off = s * STAGE_B;
        cp16(sA0 + off, Ag0 + s * 32);
        cp16(sA1 + off, Ag1 + s * 32);
        cp16(sB0 + off, Bg0 + s * 32);
        cp16(sB1 + off, Bg1 + s * 32);
        cp_commit();
    }

    for (int kt = 0; kt < NT; kt++) {
        cp_wait<STAGES - 2>();
        __syncthreads();

        uint32_t abase = sb + (uint32_t)(kt % STAGES) * STAGE_B;
        uint32_t bbase = abase + 10240;
        #pragma unroll
        for (int ks = 0; ks < 2; ks++) {
            uint32_t af[4][4];
            #pragma unroll
            for (int i = 0; i < 4; i++) {
                uint32_t r = wm * 64 + i * 16 + (lane & 15);
                uint32_t c = ks * 16 + (lane >> 4) * 8;
                ldsm_x4(af[i][0], af[i][1], af[i][2], af[i][3], abase + (r * 40 + c) * 2);
            }
            uint32_t bf[4][2];
            #pragma unroll
            for (int jp = 0; jp < 2; jp++) {
                uint32_t r = wn * 32 + jp * 16 + ((lane >> 4) & 1) * 8 + (lane & 7);
                uint32_t c = ks * 16 + ((lane >> 3) & 1) * 8;
                ldsm_x4(bf[2 * jp][0], bf[2 * jp][1], bf[2 * jp + 1][0], bf[2 * jp + 1][1],
                        bbase + (r * 40 + c) * 2);
            }
            #pragma unroll
            for (int i = 0; i < 4; i++)
                #pragma unroll
                for (int j = 0; j < 4; j++) mma16816(acc[i][j], af[i], bf[j]);
        }

        int nk = kt + STAGES - 1;
        if (nk < NT) {
            uint32_t off = (uint32_t)(nk % STAGES) * STAGE_B;
            cp16(sA0 + off, Ag0 + nk * 32);
            cp16(sA1 + off, Ag1 + nk * 32);
            cp16(sB0 + off, Bg0 + nk * 32);
            cp16(sB1 + off, Bg1 + nk * 32);
        }
        cp_commit();
    }

    #pragma unroll
    for (int i = 0; i < 4; i++) {
        int m_a = m0 + wm * 64 + i * 16 + (lane >> 2);
        int m_b = m_a + 8;
        if (MODE == 1) {
            float c0a = g_cS[m_a * 8], c0b = g_cS[m_b * 8];
            #pragma unroll
            for (int j = 0; j < 4; j++) {
                int f = n0 + wn * 32 + j * 8 + (lane & 3) * 2;
                float b0v = bias[f], b1v = bias[f + 1];
                float v0 = acc[i][j][0] + c0a * b0v;
                float v1 = acc[i][j][1] + c0a * b1v;
                float v2 = acc[i][j][2] + c0b * b0v;
                float v3 = acc[i][j][3] + c0b * b1v;
                if (f < MLPH) {
                    const float is2 = 0.70710678118654752f;
                    v0 = 0.5f * v0 * (1.f + erff(v0 * is2));
                    v1 = 0.5f * v1 * (1.f + erff(v1 * is2));
                    v2 = 0.5f * v2 * (1.f + erff(v2 * is2));
                    v3 = 0.5f * v3 * (1.f + erff(v3 * is2));
                    *(__half2*)&g_y2h[(size_t)m_a * FC2IN + f] = __floats2half2_rn(v0, v1);
                    *(__half2*)&g_y2h[(size_t)m_b * FC2IN + f] = __floats2half2_rn(v2, v3);
                } else {
                    int fq = f - MLPH;
                    float sc = (fq < 768) ? 0.125f : 1.f;   // pre-scale q by 1/sqrt(64)
                    *(__half2*)&g_qkvh[(size_t)m_a * QKVD + fq] = __floats2half2_rn(v0 * sc, v1 * sc);
                    *(__half2*)&g_qkvh[(size_t)m_b * QKVD + fq] = __floats2half2_rn(v2 * sc, v3 * sc);
                }
            }
        } else if (MODE == 2) {
            #pragma unroll
            for (int j = 0; j < 4; j++) {
                int o = n0 + wn * 32 + j * 8 + (lane & 3) * 2;
                *(float2*)&g_part[(size_t)m_a * FC2OUTF + o] = make_float2(acc[i][j][0], acc[i][j][1]);
                *(float2*)&g_part[(size_t)m_b * FC2OUTF + o] = make_float2(acc[i][j][2], acc[i][j][3]);
            }
        } else {
            #pragma unroll
            for (int j = 0; j < 4; j++) {
                int o = n0 + wn * 32 + j * 8 + (lane & 3) * 2;   // 0..767
                int seg = (o >= 384) ? 3 : (o >= 192) ? 2 : (o >= 96) ? 1 : 0;
                float Sa = g_cS[m_a * 8 + 4 + seg], Sb = g_cS[m_b * 8 + 4 + seg];
                float b0v = bias[o] + bias[o + 768];
                float b1v = bias[o + 1] + bias[o + 769];
                float2 pa = *(const float2*)&g_part[(size_t)m_a * FC2OUTF + o];
                float2 pb = *(const float2*)&g_part[(size_t)m_b * FC2OUTF + o];
                float2 xa = *(const float2*)&xres[(size_t)m_a * DIMC + o];
                float2 xb = *(const float2*)&xres[(size_t)m_b * DIMC + o];
                *(float2*)&outp[(size_t)m_a * DIMC + o] =
                    make_float2(xa.x + (acc[i][j][0] + pa.x + b0v) * Sa,
                                xa.y + (acc[i][j][1] + pa.y + b1v) * Sa);
                *(float2*)&outp[(size_t)m_b * DIMC + o] =
                    make_float2(xb.x + (acc[i][j][2] + pb.x + b0v) * Sb,
                                xb.y + (acc[i][j][3] + pb.y + b1v) * Sb);
            }
        }
    }
}

// ---------------- K6: flash attention on HMMA (proven static version) ----------------
__global__ __launch_bounds__(256) void fattn_kernel() {
    __shared__ __half Qs[128][72];
    __shared__ __half Ks[64][72];
    __shared__ __half Vs[64][72];
    int bh = blockIdx.x;
    int b = bh / 12, h = bh % 12;
    int q0 = blockIdx.y * 128;
    int tid = threadIdx.x, wid = tid >> 5, lane = tid & 31;
    const __half* base = g_qkvh + (size_t)b * 1024 * QKVD + h * 64;

    #pragma unroll
    for (int i = 0; i < 4; i++) {
        int chunk = i * 256 + tid;
        int r = chunk >> 3, c8 = (chunk & 7) * 8;
        *(uint4*)&Qs[r][c8] = *(const uint4*)(base + (size_t)(q0 + r) * QKVD + c8);
    }
    __syncthreads();

    uint32_t qbase = (uint32_t)__cvta_generic_to_shared(&Qs[0][0]);
    uint32_t kbase = (uint32_t)__cvta_generic_to_shared(&Ks[0][0]);
    uint32_t vbase = (uint32_t)__cvta_generic_to_shared(&Vs[0][0]);

    uint32_t qf[4][4];
    #pragma unroll
    for (int kk = 0; kk < 4; kk++) {
        uint32_t addr = qbase + (((uint32_t)(wid * 16 + (lane & 15))) * 72 + kk * 16 + (lane >> 4) * 8) * 2;
        ldsm_x4(qf[kk][0], qf[kk][1], qf[kk][2], qf[kk][3], addr);
    }

    float m0 = -1e30f, m1 = -1e30f, l0 = 0.f, l1 = 0.f;
    float o[8][4];
    #pragma unroll
    for (int dj = 0; dj < 8; dj++)
        #pragma unroll
        for (int t = 0; t < 4; t++) o[dj][t] = 0.f;

    for (int kt = 0; kt < 16; kt++) {
        __syncthreads();
        #pragma unroll
        for (int i = 0; i < 2; i++) {
            int chunk = i * 256 + tid;
            int r = chunk >> 3, c8 = (chunk & 7) * 8;
            const __half* rowp = base + (size_t)(kt * 64 + r) * QKVD + c8;
            *(uint4*)&Ks[r][c8] = *(const uint4*)(rowp + 768);
            *(uint4*)&Vs[r][c8] = *(const uint4*)(rowp + 1536);
        }
        __syncthreads();

        float s[8][4];
        #pragma unroll
        for (int j = 0; j < 8; j++)
            #pragma unroll
            for (int t = 0; t < 4; t++) s[j][t] = 0.f;
        #pragma unroll
        for (int kk = 0; kk < 4; kk++) {
            #pragma unroll
            for (int jp = 0; jp < 4; jp++) {
                uint32_t bf2[4];
                uint32_t r = (uint32_t)(jp * 16 + ((lane >> 4) & 1) * 8 + (lane & 7));
                uint32_t c = kk * 16 + ((lane >> 3) & 1) * 8;
                ldsm_x4(bf2[0], bf2[1], bf2[2], bf2[3], kbase + (r * 72 + c) * 2);
                mma16816(s[2 * jp], qf[kk], bf2);
                mma16816(s[2 * jp + 1], qf[kk], bf2 + 2);
            }
        }

        float tm0 = -1e30f, tm1 = -1e30f;
        #pragma unroll
        for (int j = 0; j < 8; j++) {
            tm0 = fmaxf(tm0, fmaxf(s[j][0], s[j][1]));
            tm1 = fmaxf(tm1, fmaxf(s[j][2], s[j][3]));
        }
        tm0 = fmaxf(tm0, __shfl_xor_sync(0xffffffffu, tm0, 1));
        tm0 = fmaxf(tm0, __shfl_xor_sync(0xffffffffu, tm0, 2));
        tm1 = fmaxf(tm1, __shfl_xor_sync(0xffffffffu, tm1, 1));
        tm1 = fmaxf(tm1, __shfl_xor_sync(0xffffffffu, tm1, 2));
        float nm0 = fmaxf(m0, tm0), nm1 = fmaxf(m1, tm1);
        float corr0 = __expf(m0 - nm0), corr1 = __expf(m1 - nm1);
        m0 = nm0; m1 = nm1;

        uint32_t plo[8], phi[8];
        float ps0 = 0.f, ps1 = 0.f;
        #pragma unroll
        for (int j = 0; j < 8; j++) {
            float p0 = __expf(s[j][0] - m0), p1 = __expf(s[j][1] - m0);
            float p2 = __expf(s[j][2] - m1), p3 = __expf(s[j][3] - m1);
            ps0 += p0 + p1; ps1 += p2 + p3;
            plo[j] = packh2(p0, p1);
            phi[j] = packh2(p2, p3);
        }
        l0 = l0 * corr0 + ps0;
        l1 = l1 * corr1 + ps1;
        #pragma unroll
        for (int dj = 0; dj < 8; dj++) {
            o[dj][0] *= corr0; o[dj][1] *= corr0;
            o[dj][2] *= corr1; o[dj][3] *= corr1;
        }

        #pragma unroll
        for (int jj = 0; jj < 4; jj++) {
            uint32_t a[4] = {plo[2 * jj], phi[2 * jj], plo[2 * jj + 1], phi[2 * jj + 1]};
            #pragma unroll
            for (int dj = 0; dj < 8; dj++) {
                uint32_t bfv[2];
                uint32_t addr = vbase + (((uint32_t)(jj * 16 + (lane & 15))) * 72 + dj * 8) * 2;
                ldsm_x2_trans(bfv[0], bfv[1], addr);
                mma16816(o[dj], a, bfv);
            }
        }
    }

    l0 += __shfl_xor_sync(0xffffffffu, l0, 1);
    l0 += __shfl_xor_sync(0xffffffffu, l0, 2);
    l1 += __shfl_xor_sync(0xffffffffu, l1, 1);
    l1 += __shfl_xor_sync(0xffffffffu, l1, 2);
    float inv0 = 1.f / l0, inv1 = 1.f / l1;
    int r0 = q0 + wid * 16 + (lane >> 2);
    size_t m_a = (size_t)(b * 1024 + r0) * FC2IN + MLPH + h * 64;
    size_t m_b = m_a + (size_t)8 * FC2IN;
    #pragma unroll
    for (int dj = 0; dj < 8; dj++) {
        int d = dj * 8 + (lane & 3) * 2;
        *(__half2*)&g_y2h[m_a + d] = __floats2half2_rn(o[dj][0] * inv0, o[dj][1] * inv0);
        *(__half2*)&g_y2h[m_b + d] = __floats2half2_rn(o[dj][2] * inv1, o[dj][3] * inv1);
    }
}

// ---------------- launch ----------------
extern "C" void kernel_launch(void* const* d_in, const int* in_sizes, int n_in,
                              void* d_out, int out_size) {
    const float* x = (const float*)d_in[0];
    const float* wr = (const float*)d_in[1];
    const float* gamma = (const float*)d_in[2];
    const float* beta = (const float*)d_in[3];
    const float* w1 = (const float*)d_in[4];
    const float* b1 = (const float*)d_in[5];
    const float* w2 = (const float*)d_in[6];
    const float* b2 = (const float*)d_in[7];
    float* out = (float*)d_out;

    static cudaStream_t s2 = nullptr;
    static cudaEvent_t evFork = nullptr, evJoin = nullptr, evG1 = nullptr, evG2a = nullptr;
    if (!s2) {
        cudaStreamCreateWithFlags(&s2, cudaStreamNonBlocking);
        cudaEventCreateWithFlags(&evFork, cudaEventDisableTiming);
        cudaEventCreateWithFlags(&evJoin, cudaEventDisableTiming);
        cudaEventCreateWithFlags(&evG1, cudaEventDisableTiming);
        cudaEventCreateWithFlags(&evG2a, cudaEventDisableTiming);
        cudaFuncSetAttribute(gemm_mma<1>, cudaFuncAttributeMaxDynamicSharedMemorySize, 61440);
        cudaFuncSetAttribute(gemm_mma<2>, cudaFuncAttributeMaxDynamicSharedMemorySize, 61440);
        cudaFuncSetAttribute(gemm_mma<3>, cudaFuncAttributeMaxDynamicSharedMemorySize, 61440);
    }

    constexpr int NCVT = FC1OUT * DIMC / 4 + FC2OUTF * FC2IN / 4;

    // fork 1: weight conversion concurrent with router->topk->ln
    cudaEventRecord(evFork, 0);
    cudaStreamWaitEvent(s2, evFork, 0);
    h_cvt_kernel<<<(NCVT + 255) / 256, 256, 0, s2>>>(w1, w2);
    cudaEventRecord(evJoin, s2);

    router_kernel<<<NTOK / 8, 256>>>(x, wr);
    topk_kernel<<<32, 1024>>>();
    ln_kernel<<<NTOK / 8, 256>>>(x, gamma, beta);

    cudaStreamWaitEvent(0, evJoin, 0);

    gemm_mma<1><<<dim3(FC1OUT / 128, NTOK / 128), 256, 61440>>>(b1, nullptr, nullptr);

    // fork 2: fc2 MLP-range partial concurrent with attention
    cudaEventRecord(evG1, 0);
    cudaStreamWaitEvent(s2, evG1, 0);
    gemm_mma<2><<<dim3(FC2OUTF / 128, NTOK / 128), 256, 61440, s2>>>(b2, nullptr, nullptr);
    cudaEventRecord(evG2a, s2);

    fattn_kernel<<<dim3(96, 8), 256>>>();

    cudaStreamWaitEvent(0, evG2a, 0);

    gemm_mma<3><<<dim3(FC2OUTF / 128, NTOK / 128), 256, 61440>>>(b2, x, out);
}

// round 17
// speedup vs baseline: 1.0544x; 1.0395x over previous
#include <cuda_runtime.h>
#include <cuda_fp16.h>
#include <math.h>
#include <cstdint>

#define NTOK 8192      // B*N = 8*1024
#define DIMC 768
#define FC1OUT 5376
#define MLPH 3072
#define QKVD 2304
#define FC2IN 3840
#define FC2OUTF 768    // folded FC2 output (w2[c] + w2[c+768])

// ---------------- scratch (device globals; no allocation allowed) ----------------
__device__ float g_probsT[4 * NTOK];
__device__ float g_gate[4 * NTOK];
__device__ unsigned char g_sel[4 * NTOK];
__device__ float g_cS[NTOK * 8];                 // c0..c3, S0..S3 per token
__device__ __half g_yph[NTOK * DIMC];            // fp16(LN(x) * c_seg)  (fc1 A)
__device__ __half g_y2h[NTOK * FC2IN];           // fp16([gelu(mlp) | attn_out]) (fc2 A)
__device__ __half g_qkvh[NTOK * QKVD];           // fp16 qkv (q pre-scaled by 0.125)
__device__ __half g_w1h[FC1OUT * DIMC];          // fp16 weights
__device__ __half g_w2h[FC2OUTF * FC2IN];        // fp16 folded w2: w2[c]+w2[c+768]
__device__ float g_part[NTOK * FC2OUTF];         // fc2 partial over K=0..3071

// ================= PTX helpers =================
__device__ __forceinline__ void cp16(uint32_t dst, const void* src) {
    asm volatile("cp.async.cg.shared.global [%0], [%1], 16;" :: "r"(dst), "l"(src));
}
__device__ __forceinline__ void cp_commit() { asm volatile("cp.async.commit_group;"); }
template <int N>
__device__ __forceinline__ void cp_wait() { asm volatile("cp.async.wait_group %0;" :: "n"(N)); }

__device__ __forceinline__ void ldsm_x4(uint32_t& r0, uint32_t& r1, uint32_t& r2, uint32_t& r3, uint32_t addr) {
    asm volatile("ldmatrix.sync.aligned.m8n8.x4.shared.b16 {%0,%1,%2,%3}, [%4];"
                 : "=r"(r0), "=r"(r1), "=r"(r2), "=r"(r3) : "r"(addr));
}
__device__ __forceinline__ void ldsm_x2_trans(uint32_t& r0, uint32_t& r1, uint32_t addr) {
    asm volatile("ldmatrix.sync.aligned.m8n8.x2.trans.shared.b16 {%0,%1}, [%2];"
                 : "=r"(r0), "=r"(r1) : "r"(addr));
}
__device__ __forceinline__ void mma16816(float* c, const uint32_t* a, const uint32_t* b) {
    asm volatile("mma.sync.aligned.m16n8k16.row.col.f32.f16.f16.f32 "
                 "{%0,%1,%2,%3}, {%4,%5,%6,%7}, {%8,%9}, {%0,%1,%2,%3};"
                 : "+f"(c[0]), "+f"(c[1]), "+f"(c[2]), "+f"(c[3])
                 : "r"(a[0]), "r"(a[1]), "r"(a[2]), "r"(a[3]), "r"(b[0]), "r"(b[1]));
}
__device__ __forceinline__ uint32_t packh2(float a, float b) {
    __half2 h = __floats2half2_rn(a, b);
    return *(uint32_t*)&h;
}

// ---------------- K1: router logits + softmax (float4, warp/token) ----------------
__global__ __launch_bounds__(256) void router_kernel(const float* __restrict__ x,
                                                     const float* __restrict__ wr) {
    int warp = (blockIdx.x * blockDim.x + threadIdx.x) >> 5;
    int lane = threadIdx.x & 31;
    if (warp >= NTOK) return;
    const float4* xr = (const float4*)(x + (size_t)warp * DIMC);
    const float4* w0 = (const float4*)(wr);
    const float4* w1 = (const float4*)(wr + DIMC);
    const float4* w2 = (const float4*)(wr + 2 * DIMC);
    const float4* w3 = (const float4*)(wr + 3 * DIMC);
    float acc0 = 0.f, acc1 = 0.f, acc2 = 0.f, acc3 = 0.f;
    #pragma unroll
    for (int i = 0; i < 6; i++) {
        int idx = i * 32 + lane;
        float4 xv = xr[idx];
        float4 a = w0[idx], b = w1[idx], c = w2[idx], d = w3[idx];
        acc0 += xv.x * a.x + xv.y * a.y + xv.z * a.z + xv.w * a.w;
        acc1 += xv.x * b.x + xv.y * b.y + xv.z * b.z + xv.w * b.w;
        acc2 += xv.x * c.x + xv.y * c.y + xv.z * c.z + xv.w * c.w;
        acc3 += xv.x * d.x + xv.y * d.y + xv.z * d.z + xv.w * d.w;
    }
    #pragma unroll
    for (int o = 16; o; o >>= 1) {
        acc0 += __shfl_down_sync(0xffffffffu, acc0, o);
        acc1 += __shfl_down_sync(0xffffffffu, acc1, o);
        acc2 += __shfl_down_sync(0xffffffffu, acc2, o);
        acc3 += __shfl_down_sync(0xffffffffu, acc3, o);
    }
    if (lane == 0) {
        float mx = fmaxf(fmaxf(acc0, acc1), fmaxf(acc2, acc3));
        float p0 = expf(acc0 - mx), p1 = expf(acc1 - mx), p2 = expf(acc2 - mx), p3 = expf(acc3 - mx);
        float inv = 1.f / (p0 + p1 + p2 + p3);
        int b = warp >> 10, n = warp & 1023;
        g_probsT[(b * 4 + 0) * 1024 + n] = p0 * inv;
        g_probsT[(b * 4 + 1) * 1024 + n] = p1 * inv;
        g_probsT[(b * 4 + 2) * 1024 + n] = p2 * inv;
        g_probsT[(b * 4 + 3) * 1024 + n] = p3 * inv;
    }
}

// ---------------- K2: top-512 per (b,e) by rank counting (float4 inner loop) ----------------
__global__ __launch_bounds__(1024) void topk_kernel() {
    __shared__ float sp[1024];
    int be = blockIdx.x;
    int i = threadIdx.x;
    float p = g_probsT[be * 1024 + i];
    sp[i] = p;
    __syncthreads();
    const float4* sp4 = (const float4*)sp;
    int cnt = 0;
    #pragma unroll 4
    for (int j4 = 0; j4 < 256; j4++) {
        float4 q = sp4[j4];
        int j = j4 * 4;
        cnt += (q.x > p) || (q.x == p && (j + 0) < i);
        cnt += (q.y > p) || (q.y == p && (j + 1) < i);
        cnt += (q.z > p) || (q.z == p && (j + 2) < i);
        cnt += (q.w > p) || (q.w == p && (j + 3) < i);
    }
    bool sel = cnt < 512;
    g_gate[be * 1024 + i] = sel ? p : 0.f;
    g_sel[be * 1024 + i] = sel ? 1 : 0;
}

// ---------------- K3+K4 fused: per-token stats + LayerNorm * c_seg -> fp16 ----------------
__global__ __launch_bounds__(256) void ln_kernel(const float* __restrict__ x,
                                                 const float* __restrict__ gamma,
                                                 const float* __restrict__ beta) {
    int warp = (blockIdx.x * blockDim.x + threadIdx.x) >> 5;
    int lane = threadIdx.x & 31;
    if (warp >= NTOK) return;

    float c0, c1, c2, c3;
    if (lane == 0) {
        int b = warp >> 10, n = warp & 1023;
        float cs = 0.f, ss = 0.f;
        float cArr[4], SArr[4];
        #pragma unroll
        for (int e = 3; e >= 0; e--) {
            cs += (float)g_sel[(b * 4 + e) * 1024 + n];
            ss += g_gate[(b * 4 + e) * 1024 + n];
            cArr[e] = cs;
            SArr[e] = ss;
        }
        #pragma unroll
        for (int k = 0; k < 4; k++) {
            g_cS[warp * 8 + k] = cArr[k];
            g_cS[warp * 8 + 4 + k] = SArr[k];
        }
        c0 = cArr[0]; c1 = cArr[1]; c2 = cArr[2]; c3 = cArr[3];
    }
    c0 = __shfl_sync(0xffffffffu, c0, 0);
    c1 = __shfl_sync(0xffffffffu, c1, 0);
    c2 = __shfl_sync(0xffffffffu, c2, 0);
    c3 = __shfl_sync(0xffffffffu, c3, 0);

    const float4* xr = (const float4*)(x + (size_t)warp * DIMC);
    float4 v[6];
    float s = 0.f, s2 = 0.f;
    #pragma unroll
    for (int i = 0; i < 6; i++) {
        v[i] = xr[i * 32 + lane];
        s += v[i].x + v[i].y + v[i].z + v[i].w;
        s2 += v[i].x * v[i].x + v[i].y * v[i].y + v[i].z * v[i].z + v[i].w * v[i].w;
    }
    #pragma unroll
    for (int o = 16; o; o >>= 1) {
        s += __shfl_xor_sync(0xffffffffu, s, o);
        s2 += __shfl_xor_sync(0xffffffffu, s2, o);
    }
    float mu = s * (1.f / 768.f);
    float var = s2 * (1.f / 768.f) - mu * mu;
    float rstd = rsqrtf(var + 1e-6f);
    const float4* gm = (const float4*)gamma;
    const float4* bt = (const float4*)beta;
    #pragma unroll
    for (int i = 0; i < 6; i++) {
        int idx = i * 32 + lane;
        int d = idx * 4;
        float c = (d < 96) ? c0 : (d < 192) ? c1 : (d < 384) ? c2 : c3;
        float4 g = gm[idx], b = bt[idx];
        float r0 = ((v[i].x - mu) * rstd * g.x + b.x) * c;
        float r1 = ((v[i].y - mu) * rstd * g.y + b.y) * c;
        float r2 = ((v[i].z - mu) * rstd * g.z + b.z) * c;
        float r3 = ((v[i].w - mu) * rstd * g.w + b.w) * c;
        __half2 h0 = __floats2half2_rn(r0, r1);
        __half2 h1 = __floats2half2_rn(r2, r3);
        uint2 pk = make_uint2(*(uint32_t*)&h0, *(uint32_t*)&h1);
        *(uint2*)&g_yph[(size_t)warp * DIMC + d] = pk;
    }
}

// ---------------- weight conversion: w1 -> fp16, w2 folded (c + c+768) -> fp16 ----------------
__global__ void h_cvt_kernel(const float* __restrict__ w1, const float* __restrict__ w2) {
    constexpr int N1 = FC1OUT * DIMC / 4;
    constexpr int N2 = FC2OUTF * FC2IN / 4;
    int i = blockIdx.x * blockDim.x + threadIdx.x;
    if (i < N1) {
        float4 v = ((const float4*)w1)[i];
        __half2 h01 = __floats2half2_rn(v.x, v.y);
        __half2 h23 = __floats2half2_rn(v.z, v.w);
        ((__half2*)g_w1h)[i * 2] = h01;
        ((__half2*)g_w1h)[i * 2 + 1] = h23;
    } else if (i < N1 + N2) {
        int idx = i - N1;
        float4 a = ((const float4*)w2)[idx];
        float4 b = ((const float4*)w2)[idx + N2];
        a.x += b.x; a.y += b.y; a.z += b.z; a.w += b.w;
        __half2 h01 = __floats2half2_rn(a.x, a.y);
        __half2 h23 = __floats2half2_rn(a.z, a.w);
        ((__half2*)g_w2h)[idx * 2] = h01;
        ((__half2*)g_w2h)[idx * 2 + 1] = h23;
    }
}

// ================ HMMA GEMM 128x128, BK=32, cp.async 3-stage (proven schedule) ================
// MODE 1: A=g_yph K=768, W=g_w1h, n0 offset by noff: gelu->g_y2h / ->g_qkvh; bias c0*b1
// MODE 2: fc2 partial over K=0..3071 (MLP range): raw acc -> g_part
// MODE 3: fc2 tail K=3072..3839 (attn range): out = x + (acc + part + b2fold) * S_seg
template <int MODE>
__global__ __launch_bounds__(256) void gemm_mma(const float* __restrict__ bias,
                                                const float* __restrict__ xres,
                                                float* __restrict__ outp,
                                                int noff) {
    constexpr int KDIM = (MODE == 1) ? DIMC : FC2IN;
    constexpr int KOFF = (MODE == 3) ? MLPH : 0;
    constexpr int NT = (MODE == 1) ? (DIMC / 32) : (MODE == 2) ? (MLPH / 32) : ((FC2IN - MLPH) / 32);
    constexpr int STAGES = 3;
    constexpr uint32_t STAGE_B = 20480;
    const __half* __restrict__ A = (MODE == 1) ? (const __half*)g_yph : (const __half*)g_y2h + KOFF;
    const __half* __restrict__ Wh = (MODE == 1) ? (const __half*)g_w1h : (const __half*)g_w2h + KOFF;

    extern __shared__ char smem[];
    uint32_t sb = (uint32_t)__cvta_generic_to_shared(smem);

    int tid = threadIdx.x, wid = tid >> 5, lane = tid & 31;
    int m0 = blockIdx.y * 128, n0 = blockIdx.x * 128 + noff;
    int wm = wid & 1, wn = wid >> 1;

    int cr = tid >> 2, cc = (tid & 3) * 8;
    const __half* Ag0 = A + (size_t)(m0 + cr) * KDIM + cc;
    const __half* Ag1 = A + (size_t)(m0 + cr + 64) * KDIM + cc;
    const __half* Bg0 = Wh + (size_t)(n0 + cr) * KDIM + cc;
    const __half* Bg1 = Wh + (size_t)(n0 + cr + 64) * KDIM + cc;
    uint32_t sA0 = sb + cr * 80 + cc * 2;
    uint32_t sA1 = sA0 + 64 * 80;
    uint32_t sB0 = sb + 10240 + cr * 80 + cc * 2;
    uint32_t sB1 = sB0 + 64 * 80;

    float acc[4][4][4];
    #pragma unroll
    for (int i = 0; i < 4; i++)
        #pragma unroll
        for (int j = 0; j < 4; j++)
            #pragma unroll
            for (int t = 0; t < 4; t++) acc[i][j][t] = 0.f;

    #pragma unroll
    for (int s = 0; s < STAGES - 1; s++) {
        uint32_t off = s * STAGE_B;
        cp16(sA0 + off, Ag0 + s * 32);
        cp16(sA1 + off, Ag1 + s * 32);
        cp16(sB0 + off, Bg0 + s * 32);
        cp16(sB1 + off, Bg1 + s * 32);
        cp_commit();
    }

    for (int kt = 0; kt < NT; kt++) {
        cp_wait<STAGES - 2>();
        __syncthreads();

        uint32_t abase = sb + (uint32_t)(kt % STAGES) * STAGE_B;
        uint32_t bbase = abase + 10240;
        #pragma unroll
        for (int ks = 0; ks < 2; ks++) {
            uint32_t af[4][4];
            #pragma unroll
            for (int i = 0; i < 4; i++) {
                uint32_t r = wm * 64 + i * 16 + (lane & 15);
                uint32_t c = ks * 16 + (lane >> 4) * 8;
                ldsm_x4(af[i][0], af[i][1], af[i][2], af[i][3], abase + (r * 40 + c) * 2);
            }
            uint32_t bf[4][2];
            #pragma unroll
            for (int jp = 0; jp < 2; jp++) {
                uint32_t r = wn * 32 + jp * 16 + ((lane >> 4) & 1) * 8 + (lane & 7);
                uint32_t c = ks * 16 + ((lane >> 3) & 1) * 8;
                ldsm_x4(bf[2 * jp][0], bf[2 * jp][1], bf[2 * jp + 1][0], bf[2 * jp + 1][1],
                        bbase + (r * 40 + c) * 2);
            }
            #pragma unroll
            for (int i = 0; i < 4; i++)
                #pragma unroll
                for (int j = 0; j < 4; j++) mma16816(acc[i][j], af[i], bf[j]);
        }

        int nk = kt + STAGES - 1;
        if (nk < NT) {
            uint32_t off = (uint32_t)(nk % STAGES) * STAGE_B;
            cp16(sA0 + off, Ag0 + nk * 32);
            cp16(sA1 + off, Ag1 + nk * 32);
            cp16(sB0 + off, Bg0 + nk * 32);
            cp16(sB1 + off, Bg1 + nk * 32);
        }
        cp_commit();
    }

    #pragma unroll
    for (int i = 0; i < 4; i++) {
        int m_a = m0 + wm * 64 + i * 16 + (lane >> 2);
        int m_b = m_a + 8;
        if (MODE == 1) {
            float c0a = g_cS[m_a * 8], c0b = g_cS[m_b * 8];
            #pragma unroll
            for (int j = 0; j < 4; j++) {
                int f = n0 + wn * 32 + j * 8 + (lane & 3) * 2;
                float b0v = bias[f], b1v = bias[f + 1];
                float v0 = acc[i][j][0] + c0a * b0v;
                float v1 = acc[i][j][1] + c0a * b1v;
                float v2 = acc[i][j][2] + c0b * b0v;
                float v3 = acc[i][j][3] + c0b * b1v;
                if (f < MLPH) {
                    const float is2 = 0.70710678118654752f;
                    v0 = 0.5f * v0 * (1.f + erff(v0 * is2));
                    v1 = 0.5f * v1 * (1.f + erff(v1 * is2));
                    v2 = 0.5f * v2 * (1.f + erff(v2 * is2));
                    v3 = 0.5f * v3 * (1.f + erff(v3 * is2));
                    *(__half2*)&g_y2h[(size_t)m_a * FC2IN + f] = __floats2half2_rn(v0, v1);
                    *(__half2*)&g_y2h[(size_t)m_b * FC2IN + f] = __floats2half2_rn(v2, v3);
                } else {
                    int fq = f - MLPH;
                    float sc = (fq < 768) ? 0.125f : 1.f;   // pre-scale q by 1/sqrt(64)
                    *(__half2*)&g_qkvh[(size_t)m_a * QKVD + fq] = __floats2half2_rn(v0 * sc, v1 * sc);
                    *(__half2*)&g_qkvh[(size_t)m_b * QKVD + fq] = __floats2half2_rn(v2 * sc, v3 * sc);
                }
            }
        } else if (MODE == 2) {
            #pragma unroll
            for (int j = 0; j < 4; j++) {
                int o = n0 + wn * 32 + j * 8 + (lane & 3) * 2;
                *(float2*)&g_part[(size_t)m_a * FC2OUTF + o] = make_float2(acc[i][j][0], acc[i][j][1]);
                *(float2*)&g_part[(size_t)m_b * FC2OUTF + o] = make_float2(acc[i][j][2], acc[i][j][3]);
            }
        } else {
            #pragma unroll
            for (int j = 0; j < 4; j++) {
                int o = n0 + wn * 32 + j * 8 + (lane & 3) * 2;   // 0..767
                int seg = (o >= 384) ? 3 : (o >= 192) ? 2 : (o >= 96) ? 1 : 0;
                float Sa = g_cS[m_a * 8 + 4 + seg], Sb = g_cS[m_b * 8 + 4 + seg];
                float b0v = bias[o] + bias[o + 768];
                float b1v = bias[o + 1] + bias[o + 769];
                float2 pa = *(const float2*)&g_part[(size_t)m_a * FC2OUTF + o];
                float2 pb = *(const float2*)&g_part[(size_t)m_b * FC2OUTF + o];
                float2 xa = *(const float2*)&xres[(size_t)m_a * DIMC + o];
                float2 xb = *(const float2*)&xres[(size_t)m_b * DIMC + o];
                *(float2*)&outp[(size_t)m_a * DIMC + o] =
                    make_float2(xa.x + (acc[i][j][0] + pa.x + b0v) * Sa,
                                xa.y + (acc[i][j][1] + pa.y + b1v) * Sa);
                *(float2*)&outp[(size_t)m_b * DIMC + o] =
                    make_float2(xb.x + (acc[i][j][2] + pb.x + b0v) * Sb,
                                xb.y + (acc[i][j][3] + pb.y + b1v) * Sb);
            }
        }
    }
}

// ---------------- K6: flash attention on HMMA (proven static version) ----------------
__global__ __launch_bounds__(256) void fattn_kernel() {
    __shared__ __half Qs[128][72];
    __shared__ __half Ks[64][72];
    __shared__ __half Vs[64][72];
    int bh = blockIdx.x;
    int b = bh / 12, h = bh % 12;
    int q0 = blockIdx.y * 128;
    int tid = threadIdx.x, wid = tid >> 5, lane = tid & 31;
    const __half* base = g_qkvh + (size_t)b * 1024 * QKVD + h * 64;

    #pragma unroll
    for (int i = 0; i < 4; i++) {
        int chunk = i * 256 + tid;
        int r = chunk >> 3, c8 = (chunk & 7) * 8;
        *(uint4*)&Qs[r][c8] = *(const uint4*)(base + (size_t)(q0 + r) * QKVD + c8);
    }
    __syncthreads();

    uint32_t qbase = (uint32_t)__cvta_generic_to_shared(&Qs[0][0]);
    uint32_t kbase = (uint32_t)__cvta_generic_to_shared(&Ks[0][0]);
    uint32_t vbase = (uint32_t)__cvta_generic_to_shared(&Vs[0][0]);

    uint32_t qf[4][4];
    #pragma unroll
    for (int kk = 0; kk < 4; kk++) {
        uint32_t addr = qbase + (((uint32_t)(wid * 16 + (lane & 15))) * 72 + kk * 16 + (lane >> 4) * 8) * 2;
        ldsm_x4(qf[kk][0], qf[kk][1], qf[kk][2], qf[kk][3], addr);
    }

    float m0 = -1e30f, m1 = -1e30f, l0 = 0.f, l1 = 0.f;
    float o[8][4];
    #pragma unroll
    for (int dj = 0; dj < 8; dj++)
        #pragma unroll
        for (int t = 0; t < 4; t++) o[dj][t] = 0.f;

    for (int kt = 0; kt < 16; kt++) {
        __syncthreads();
        #pragma unroll
        for (int i = 0; i < 2; i++) {
            int chunk = i * 256 + tid;
            int r = chunk >> 3, c8 = (chunk & 7) * 8;
            const __half* rowp = base + (size_t)(kt * 64 + r) * QKVD + c8;
            *(uint4*)&Ks[r][c8] = *(const uint4*)(rowp + 768);
            *(uint4*)&Vs[r][c8] = *(const uint4*)(rowp + 1536);
        }
        __syncthreads();

        float s[8][4];
        #pragma unroll
        for (int j = 0; j < 8; j++)
            #pragma unroll
            for (int t = 0; t < 4; t++) s[j][t] = 0.f;
        #pragma unroll
        for (int kk = 0; kk < 4; kk++) {
            #pragma unroll
            for (int jp = 0; jp < 4; jp++) {
                uint32_t bf2[4];
                uint32_t r = (uint32_t)(jp * 16 + ((lane >> 4) & 1) * 8 + (lane & 7));
                uint32_t c = kk * 16 + ((lane >> 3) & 1) * 8;
                ldsm_x4(bf2[0], bf2[1], bf2[2], bf2[3], kbase + (r * 72 + c) * 2);
                mma16816(s[2 * jp], qf[kk], bf2);
                mma16816(s[2 * jp + 1], qf[kk], bf2 + 2);
            }
        }

        float tm0 = -1e30f, tm1 = -1e30f;
        #pragma unroll
        for (int j = 0; j < 8; j++) {
            tm0 = fmaxf(tm0, fmaxf(s[j][0], s[j][1]));
            tm1 = fmaxf(tm1, fmaxf(s[j][2], s[j][3]));
        }
        tm0 = fmaxf(tm0, __shfl_xor_sync(0xffffffffu, tm0, 1));
        tm0 = fmaxf(tm0, __shfl_xor_sync(0xffffffffu, tm0, 2));
        tm1 = fmaxf(tm1, __shfl_xor_sync(0xffffffffu, tm1, 1));
        tm1 = fmaxf(tm1, __shfl_xor_sync(0xffffffffu, tm1, 2));
        float nm0 = fmaxf(m0, tm0), nm1 = fmaxf(m1, tm1);
        float corr0 = __expf(m0 - nm0), corr1 = __expf(m1 - nm1);
        m0 = nm0; m1 = nm1;

        uint32_t plo[8], phi[8];
        float ps0 = 0.f, ps1 = 0.f;
        #pragma unroll
        for (int j = 0; j < 8; j++) {
            float p0 = __expf(s[j][0] - m0), p1 = __expf(s[j][1] - m0);
            float p2 = __expf(s[j][2] - m1), p3 = __expf(s[j][3] - m1);
            ps0 += p0 + p1; ps1 += p2 + p3;
            plo[j] = packh2(p0, p1);
            phi[j] = packh2(p2, p3);
        }
        l0 = l0 * corr0 + ps0;
        l1 = l1 * corr1 + ps1;
        #pragma unroll
        for (int dj = 0; dj < 8; dj++) {
            o[dj][0] *= corr0; o[dj][1] *= corr0;
            o[dj][2] *= corr1; o[dj][3] *= corr1;
        }

        #pragma unroll
        for (int jj = 0; jj < 4; jj++) {
            uint32_t a[4] = {plo[2 * jj], phi[2 * jj], plo[2 * jj + 1], phi[2 * jj + 1]};
            #pragma unroll
            for (int dj = 0; dj < 8; dj++) {
                uint32_t bfv[2];
                uint32_t addr = vbase + (((uint32_t)(jj * 16 + (lane & 15))) * 72 + dj * 8) * 2;
                ldsm_x2_trans(bfv[0], bfv[1], addr);
                mma16816(o[dj], a, bfv);
            }
        }
    }

    l0 += __shfl_xor_sync(0xffffffffu, l0, 1);
    l0 += __shfl_xor_sync(0xffffffffu, l0, 2);
    l1 += __shfl_xor_sync(0xffffffffu, l1, 1);
    l1 += __shfl_xor_sync(0xffffffffu, l1, 2);
    float inv0 = 1.f / l0, inv1 = 1.f / l1;
    int r0 = q0 + wid * 16 + (lane >> 2);
    size_t m_a = (size_t)(b * 1024 + r0) * FC2IN + MLPH + h * 64;
    size_t m_b = m_a + (size_t)8 * FC2IN;
    #pragma unroll
    for (int dj = 0; dj < 8; dj++) {
        int d = dj * 8 + (lane & 3) * 2;
        *(__half2*)&g_y2h[m_a + d] = __floats2half2_rn(o[dj][0] * inv0, o[dj][1] * inv0);
        *(__half2*)&g_y2h[m_b + d] = __floats2half2_rn(o[dj][2] * inv1, o[dj][3] * inv1);
    }
}

// ---------------- launch ----------------
extern "C" void kernel_launch(void* const* d_in, const int* in_sizes, int n_in,
                              void* d_out, int out_size) {
    const float* x = (const float*)d_in[0];
    const float* wr = (const float*)d_in[1];
    const float* gamma = (const float*)d_in[2];
    const float* beta = (const float*)d_in[3];
    const float* w1 = (const float*)d_in[4];
    const float* b1 = (const float*)d_in[5];
    const float* w2 = (const float*)d_in[6];
    const float* b2 = (const float*)d_in[7];
    float* out = (float*)d_out;

    static cudaStream_t s2 = nullptr;
    static cudaEvent_t evFork = nullptr, evCvt = nullptr, evLn = nullptr, evG2a = nullptr;
    if (!s2) {
        cudaStreamCreateWithFlags(&s2, cudaStreamNonBlocking);
        cudaEventCreateWithFlags(&evFork, cudaEventDisableTiming);
        cudaEventCreateWithFlags(&evCvt, cudaEventDisableTiming);
        cudaEventCreateWithFlags(&evLn, cudaEventDisableTiming);
        cudaEventCreateWithFlags(&evG2a, cudaEventDisableTiming);
        cudaFuncSetAttribute(gemm_mma<1>, cudaFuncAttributeMaxDynamicSharedMemorySize, 61440);
        cudaFuncSetAttribute(gemm_mma<2>, cudaFuncAttributeMaxDynamicSharedMemorySize, 61440);
        cudaFuncSetAttribute(gemm_mma<3>, cudaFuncAttributeMaxDynamicSharedMemorySize, 61440);
    }

    constexpr int NCVT = FC1OUT * DIMC / 4 + FC2OUTF * FC2IN / 4;

    // fork: weight conversion on s2, concurrent with router->topk->ln
    cudaEventRecord(evFork, 0);
    cudaStreamWaitEvent(s2, evFork, 0);
    h_cvt_kernel<<<(NCVT + 255) / 256, 256, 0, s2>>>(w1, w2);
    cudaEventRecord(evCvt, s2);

    router_kernel<<<NTOK / 8, 256>>>(x, wr);
    topk_kernel<<<32, 1024>>>();
    ln_kernel<<<NTOK / 8, 256>>>(x, gamma, beta);
    cudaEventRecord(evLn, 0);

    // main pipeline: qkv half of gemm1 -> attention
    cudaStreamWaitEvent(0, evCvt, 0);
    gemm_mma<1><<<dim3((FC1OUT - MLPH) / 128, NTOK / 128), 256, 61440>>>(b1, nullptr, nullptr, MLPH);

    // side pipeline: mlp half of gemm1 -> fc2 MLP-range partial
    cudaStreamWaitEvent(s2, evLn, 0);
    gemm_mma<1><<<dim3(MLPH / 128, NTOK / 128), 256, 61440, s2>>>(b1, nullptr, nullptr, 0);
    gemm_mma<2><<<dim3(FC2OUTF / 128, NTOK / 128), 256, 61440, s2>>>(b2, nullptr, nullptr, 0);
    cudaEventRecord(evG2a, s2);

    fattn_kernel<<<dim3(96, 8), 256>>>();

    // join: fc2 attn-range tail fuses partial + residual -> out
    cudaStreamWaitEvent(0, evG2a, 0);
    gemm_mma<3><<<dim3(FC2OUTF / 128, NTOK / 128), 256, 61440>>>(b2, x, out, 0);
}